// round 15
// baseline (speedup 1.0000x reference)
#include <cuda_runtime.h>
#include <cuda_bf16.h>
#include <cstdint>

// Problem constants: B=16 graphs, N=4096 nodes/graph, 64 features, k=10.
#define KNN_K      10
#define BGRAPHS    16
#define FEATS      64
#define MAX_TOTAL  65536
#define NODES      4096
#define KTPB       1024           // knn: 32 warps/block, warp-per-query
#define NBUCKET    1024
#define SLABS      64             // x-slabs per graph
#define SLABN      64             // points per slab
#define NBR_STRIDE 12             // padded neighbor stride (16B-aligned int4 x3)
#define EXIT_MARGIN 1e-4f         // covers f32 cancellation in computed d2
#define INF_KEY    0x7f800000ffffffffULL

// Scratch (device globals: no allocation allowed in kernel_launch)
__device__ float  g_sum[MAX_TOTAL * FEATS];      // 16 MB accumulators
__device__ int    g_cnt[MAX_TOTAL];              // reverse-degree counts
__device__ int4   g_nbr4[MAX_TOTAL * 3];         // knn lists, stride 12 ints
__device__ float4 g_spos[MAX_TOTAL];             // x-sorted {x,y,z,|p|^2}
__device__ int    g_sidx[MAX_TOTAL];             // x-rank -> orig local idx
__device__ float4 g_spos2[MAX_TOTAL];            // slab/y-sorted positions
__device__ int    g_sid2[MAX_TOTAL];             // slab/y-rank -> orig local idx
__device__ float  g_slabx[BGRAPHS * SLABS * 2];  // per-slab exact {xmin, xmax}

__device__ __forceinline__ int xbucket(float x) {
    int bk = (int)floorf((x + 4.0f) * (NBUCKET / 8.0f));
    return max(0, min(NBUCKET - 1, bk));
}
// monotone u32 mapping of float (handles negatives)
__device__ __forceinline__ unsigned ymap(float y) {
    unsigned u = __float_as_uint(y);
    return (u & 0x80000000u) ? ~u : (u | 0x80000000u);
}

// ---------------------------------------------------------------------------
// K0: phase A — counting-sort points of each graph by x-bucket (1024 buckets),
// w = |p|^2 with exact reference rounding. Phase B — per 64-rank slab,
// warp-bitonic sort by y (exact, ties by rank), emit g_spos2/g_sid2 and exact
// per-slab x-min/max.
// ---------------------------------------------------------------------------
__global__ void __launch_bounds__(256) sort_kernel(const float* __restrict__ pos) {
    __shared__ int cnt[NBUCKET];
    __shared__ int tsum[256];
    __shared__ int off[NBUCKET];

    const int b   = blockIdx.x;
    const int tid = threadIdx.x;        // 256 threads
    const float* pg = pos + (size_t)b * NODES * 3;

#pragma unroll
    for (int i = 0; i < NBUCKET / 256; ++i) cnt[tid + i * 256] = 0;
    __syncthreads();

    for (int j = tid; j < NODES; j += 256)
        atomicAdd(&cnt[xbucket(pg[3 * j])], 1);
    __syncthreads();

    {   // two-level exclusive prefix: thread t owns bins [4t, 4t+4)
        int c0 = cnt[4 * tid], c1 = cnt[4 * tid + 1];
        int c2 = cnt[4 * tid + 2], c3 = cnt[4 * tid + 3];
        tsum[tid] = c0 + c1 + c2 + c3;
        __syncthreads();
        for (int d = 1; d < 256; d <<= 1) {
            int v = (tid >= d) ? tsum[tid - d] : 0;
            __syncthreads();
            tsum[tid] += v;
            __syncthreads();
        }
        int base = tsum[tid] - (c0 + c1 + c2 + c3);
        off[4 * tid]     = base;
        off[4 * tid + 1] = base + c0;
        off[4 * tid + 2] = base + c0 + c1;
        off[4 * tid + 3] = base + c0 + c1 + c2;
    }
    __syncthreads();

    for (int j = tid; j < NODES; j += 256) {
        float x = pg[3 * j], y = pg[3 * j + 1], z = pg[3 * j + 2];
        float w = __fadd_rn(__fadd_rn(__fmul_rn(x, x), __fmul_rn(y, y)),
                            __fmul_rn(z, z));        // == jnp.sum(pos*pos)
        int p = atomicAdd(&off[xbucket(x)], 1);
        g_spos[b * NODES + p] = make_float4(x, y, z, w);
        g_sidx[b * NODES + p] = j;
    }
    __syncthreads();

    // ---- phase B: per-slab y-sort (warp handles one slab, 8 slabs/warp) ----
    const int wp = tid >> 5;
    const int l  = tid & 31;
    for (int s = wp; s < SLABS; s += 8) {
        int base = b * NODES + s * SLABN;
        float4 f0 = g_spos[base + l];
        float4 f1 = g_spos[base + 32 + l];

        float xl = fminf(f0.x, f1.x), xh = fmaxf(f0.x, f1.x);
#pragma unroll
        for (int o = 16; o; o >>= 1) {
            xl = fminf(xl, __shfl_xor_sync(0xffffffffu, xl, o));
            xh = fmaxf(xh, __shfl_xor_sync(0xffffffffu, xh, o));
        }
        if (l == 0) {
            g_slabx[(b * SLABS + s) * 2]     = xl;
            g_slabx[(b * SLABS + s) * 2 + 1] = xh;
        }

        uint64_t v0 = ((uint64_t)ymap(f0.y) << 32) | (unsigned)(s * SLABN + l);
        uint64_t v1 = ((uint64_t)ymap(f1.y) << 32) | (unsigned)(s * SLABN + 32 + l);
#pragma unroll
        for (int k = 2; k <= 64; k <<= 1) {
#pragma unroll
            for (int j = k >> 1; j > 0; j >>= 1) {
                if (j == 32) {
                    uint64_t mn = v0 < v1 ? v0 : v1;
                    uint64_t mx = v0 < v1 ? v1 : v0;
                    v0 = mn; v1 = mx;
                } else {
                    uint64_t w0 = __shfl_xor_sync(0xffffffffu, v0, j);
                    bool asc0 = ((l & k) == 0);
                    bool keep0 = (((l & j) == 0) == asc0);
                    bool lt0 = v0 < w0;
                    v0 = (keep0 == lt0) ? v0 : w0;
                    uint64_t w1 = __shfl_xor_sync(0xffffffffu, v1, j);
                    bool asc1 = (((32 + l) & k) == 0);
                    bool keep1 = (((l & j) == 0) == asc1);
                    bool lt1 = v1 < w1;
                    v1 = (keep1 == lt1) ? v1 : w1;
                }
            }
        }
        int r0 = (int)(v0 & 0xFFFFu), r1 = (int)(v1 & 0xFFFFu);
        g_spos2[base + l]      = g_spos[b * NODES + r0];
        g_sid2 [base + l]      = g_sidx[b * NODES + r0];
        g_spos2[base + 32 + l] = g_spos[b * NODES + r1];
        g_sid2 [base + 32 + l] = g_sidx[b * NODES + r1];
    }
}

// ---------------------------------------------------------------------------
// K1: WARP-PER-QUERY 2-D pruned kNN.
//   Block = 32 warps = 32 consecutive slab-ranks (queries) of one graph;
//   stages the graph's slab/y-sorted positions (72KB) in smem.
//   Warp-distributed top-10: lane l holds the l-th smallest u64 key
//   (d2_bits<<32 | orig_idx) of a globally sorted 32-element list (INF-fill).
//   Insert = ballot(kd <= cand) -> popc -> shfl_up shift: ~12 instr
//   warp-wide; a candidate that is stale vs the current 10th simply lands at
//   lane >= 10 (sorted-list invariant keeps it exact and harmless).
//   Per slab: exact gx from slab x-range; smem binary search to
//   ystart = qy - sqrt_ru(thr + margin); rounds of 32 candidates (one per
//   lane, y-ascending); after each round exit when
//   (y_lastvalid - qy)^2 + gx^2 >= thr + margin (y exact-sorted => safe).
//   Slab expansion up/down with exact suffix-min/prefix-max x bounds.
//   All control is scalar per warp (one query) -> zero warp-union inflation,
//   zero SIMT insert tax, per-query-granular load balance.
// d2 = (qsq+w) - 2*dot with reference rounding; self excluded by rank;
// ties exact under the u64 (d2, orig_idx) total order == top_k semantics.
// ---------------------------------------------------------------------------
__global__ void __launch_bounds__(KTPB) knn_kernel(int dummy) {
    extern __shared__ float4 sm[];
    float4*         sp     = sm;                            // 4096 float4 (64KB)
    unsigned short* ssid16 = (unsigned short*)(sm + NODES); // 8KB
    __shared__ float sxlo[SLABS], sxhi[SLABS], sufmin[SLABS], prefmax[SLABS];

    const int tid  = threadIdx.x;
    const int wid  = tid >> 5;
    const int lane = tid & 31;
    const int blocksPerGraph = NODES / 32;      // 128
    const int b    = blockIdx.x / blocksPerGraph;
    const int qr   = (blockIdx.x % blocksPerGraph) * 32 + wid;  // my query rank
    const int gbase = b * NODES;
    const unsigned FULL = 0xffffffffu;

    // ---- fused zeroing of accumulators + counts (block's 32 nodes) ----
    {
        int nb = blockIdx.x * 32;               // graph-aligned
        float4* dst = reinterpret_cast<float4*>(g_sum) + (size_t)nb * (FEATS / 4);
        if (tid < 512) dst[tid] = make_float4(0.f, 0.f, 0.f, 0.f);
        if (tid < 32) g_cnt[nb + tid] = 0;
    }

    // ---- stage slab-sorted positions + ids + slab ranges ----
    for (int i = tid; i < NODES; i += KTPB) {
        sp[i] = g_spos2[gbase + i];
        ssid16[i] = (unsigned short)g_sid2[gbase + i];
    }
    if (tid < SLABS) {
        sxlo[tid] = g_slabx[(b * SLABS + tid) * 2];
        sxhi[tid] = g_slabx[(b * SLABS + tid) * 2 + 1];
    }
    __syncthreads();
    if (tid == 0) {
        float m = 1e30f;
        for (int s = SLABS - 1; s >= 0; --s) { m = fminf(m, sxlo[s]); sufmin[s] = m; }
        float M = -1e30f;
        for (int s = 0; s < SLABS; ++s) { M = fmaxf(M, sxhi[s]); prefmax[s] = M; }
    }
    __syncthreads();

    // ---- my query (all lanes broadcast-load the same smem) ----
    float4 qv = sp[qr];
    const float qx = qv.x, qyv = qv.y, qz = qv.z, qsq = qv.w;

    uint64_t kd = INF_KEY;                      // distributed sorted 32-list
    float thr = __int_as_float(0x7f800000);

    auto scan_slab = [&](int s) {
        float gx = fmaxf(fmaxf(sxlo[s] - qx, qx - sxhi[s]), 0.0f);
        float gx2 = gx * gx;
        if (gx2 >= thr + EXIT_MARGIN) return;
        float ystart = qyv - __fsqrt_ru(thr + EXIT_MARGIN);  // inf-safe
        const float4* sb = sp + s * SLABN;
        int lo = 0;
#pragma unroll
        for (int st = 32; st; st >>= 1) {
            int m = lo + st;
            if (sb[m - 1].y < ystart) lo = m;   // lo <= 64
        }
        for (int base = lo; base < SLABN; base += 32) {
            int idx = base + lane;
            bool valid = (idx < SLABN);
            uint64_t candkey = INF_KEY;
            if (valid) {
                float4 p = sb[idx];
                float dot = __fmaf_rn(qz, p.z,
                             __fmaf_rn(qyv, p.y, __fmul_rn(qx, p.x)));
                float d2  = __fmaf_rn(-2.0f, dot, __fadd_rn(qsq, p.w));
                int rank = s * SLABN + idx;
                valid = (d2 < thr) && (rank != qr);
                candkey = ((uint64_t)__float_as_uint(d2) << 32)
                        | (unsigned)ssid16[rank];
            }
            unsigned bal = __ballot_sync(FULL, valid);
            while (bal) {
                int src = __ffs(bal) - 1; bal &= bal - 1;
                uint64_t cand = __shfl_sync(FULL, candkey, src);
                uint64_t k9   = __shfl_sync(FULL, kd, 9);
                if (cand < k9) {                 // warp-uniform
                    uint64_t up = __shfl_up_sync(FULL, kd, 1);
                    unsigned b2 = __ballot_sync(FULL, kd <= cand);
                    int p = __popc(b2);
                    kd = (lane < p) ? kd : (lane == p ? cand : up);
                }
            }
            uint64_t t9 = __shfl_sync(FULL, kd, 9);
            thr = __uint_as_float((unsigned)(t9 >> 32));
            int lastidx = min(base + 31, SLABN - 1);
            float g = fmaxf(sb[lastidx].y - qyv, 0.0f);
            if (__fmaf_rn(g, g, gx2) >= thr + EXIT_MARGIN) break;
        }
    };

    // own slab, then expansion with exact x bounds (all warp-scalar)
    const int s0 = qr >> 6;
    scan_slab(s0);
    for (int s = s0 + 1; s < SLABS; ++s) {
        float gf = fmaxf(sufmin[s] - qx, 0.0f);
        if (gf * gf >= thr + EXIT_MARGIN) break;
        scan_slab(s);
    }
    for (int s = s0 - 1; s >= 0; --s) {
        float gf = fmaxf(qx - prefmax[s], 0.0f);
        if (gf * gf >= thr + EXIT_MARGIN) break;
        scan_slab(s);
    }

    // ---- write: lanes 0..9 hold the exact sorted top-10 ----
    const int my_oid = gbase + (int)ssid16[qr];
    if (lane < KNN_K) {
        int* gn = reinterpret_cast<int*>(g_nbr4);
        gn[my_oid * NBR_STRIDE + lane] = gbase + (int)(unsigned)(kd & 0xffffffffu);
    }
}

// ---------------------------------------------------------------------------
// K2: scatter x[query] into g_sum[neighbor] with vectorized L2 reductions,
// plus reverse-degree counting. Neighbor list loaded as 3x int4.
// ---------------------------------------------------------------------------
__global__ void scatter_kernel(const float* __restrict__ x, int total) {
    int t = blockIdx.x * blockDim.x + threadIdx.x;
    int q = t >> 4;
    int c = t & 15;
    if (q >= total) return;

    float4 v = reinterpret_cast<const float4*>(x)[q * (FEATS / 4) + c];
    const int4* nb4 = &g_nbr4[q * 3];
    int4 A = nb4[0], B = nb4[1], C = nb4[2];
    int js[KNN_K] = {A.x, A.y, A.z, A.w, B.x, B.y, B.z, B.w, C.x, C.y};

#pragma unroll
    for (int n = 0; n < KNN_K; ++n) {
        int j = js[n];
        float* p = g_sum + (size_t)j * FEATS + c * 4;
        asm volatile("red.global.add.v4.f32 [%0], {%1, %2, %3, %4};"
                     :: "l"(p), "f"(v.x), "f"(v.y), "f"(v.z), "f"(v.w)
                     : "memory");
        if (c == 0)
            asm volatile("red.global.add.u32 [%0], %1;"
                         :: "l"(&g_cnt[j]), "r"(1) : "memory");
    }
}

// ---------------------------------------------------------------------------
// K3: out[r] = sum_d | x[r,d] - sum[r,d] / max(cnt[r],1) |   (warp per node)
// ---------------------------------------------------------------------------
__global__ void out_kernel(const float* __restrict__ x, float* __restrict__ out,
                           int total) {
    int node = (blockIdx.x * blockDim.x + threadIdx.x) >> 5;
    int lane = threadIdx.x & 31;
    if (node >= total) return;

    float c   = (float)g_cnt[node];
    float inv = 1.0f / fmaxf(c, 1.0f);

    const float* xr = x + (size_t)node * FEATS;
    const float* sr = g_sum + (size_t)node * FEATS;

    float acc = fabsf(xr[lane]      - sr[lane]      * inv)
              + fabsf(xr[lane + 32] - sr[lane + 32] * inv);
#pragma unroll
    for (int o = 16; o > 0; o >>= 1) acc += __shfl_xor_sync(0xffffffffu, acc, o);
    if (lane == 0) out[node] = acc;
}

// ---------------------------------------------------------------------------
extern "C" void kernel_launch(void* const* d_in, const int* in_sizes, int n_in,
                              void* d_out, int out_size) {
    const float* x   = (const float*)d_in[0];   // [total, 64] fp32
    const float* pos = (const float*)d_in[1];   // [total, 3]  fp32

    const int total = in_sizes[0] / FEATS;      // 65536
    float* out = (float*)d_out;

    // K0: x counting sort + per-slab y sort + exact slab ranges
    sort_kernel<<<BGRAPHS, 256>>>(pos);

    // K1: warp-per-query 2-D pruned kNN (dynamic smem 72KB, 1024 thr/block)
    size_t smem = (size_t)NODES * sizeof(float4) + NODES * sizeof(unsigned short);
    cudaFuncSetAttribute(knn_kernel, cudaFuncAttributeMaxDynamicSharedMemorySize,
                         (int)smem);
    knn_kernel<<<total / 32, KTPB, smem>>>(0);

    // K2: vectorized atomic scatter + counts (16 lanes per query)
    int threads2 = total * 16;
    scatter_kernel<<<(threads2 + 127) / 128, 128>>>(x, total);

    // K3: finalize L1 norm (warp per node)
    out_kernel<<<(total * 32 + 255) / 256, 256>>>(x, out, total);
}

// round 16
// speedup vs baseline: 1.2938x; 1.2938x over previous
#include <cuda_runtime.h>
#include <cuda_bf16.h>
#include <cstdint>

// Problem constants: B=16 graphs, N=4096 nodes/graph, 64 features, k=10.
#define KNN_K      10
#define BGRAPHS    16
#define FEATS      64
#define MAX_TOTAL  65536
#define NODES      4096
#define QPB        256            // queries per block == threads per block (knn)
#define NBUCKET    1024
#define SLABS      64             // x-slabs per graph
#define SLABN      64             // points per slab
#define NBR_STRIDE 12             // padded neighbor stride (16B-aligned int4 x3)
#define EXIT_MARGIN 1e-4f         // covers f32 cancellation in computed d2

// Scratch (device globals: no allocation allowed in kernel_launch)
__device__ float  g_sum[MAX_TOTAL * FEATS];      // 16 MB accumulators
__device__ int    g_cnt[MAX_TOTAL];              // reverse-degree counts
__device__ int4   g_nbr4[MAX_TOTAL * 3];         // knn lists, stride 12 ints
__device__ float4 g_spos[MAX_TOTAL];             // x-sorted {x,y,z,|p|^2}
__device__ int    g_sidx[MAX_TOTAL];             // x-rank -> orig local idx
__device__ float4 g_spos2[MAX_TOTAL];            // slab/y-sorted positions
__device__ int    g_sid2[MAX_TOTAL];             // slab/y-rank -> orig local idx
__device__ float  g_slabx[BGRAPHS * SLABS * 2];  // per-slab exact {xmin, xmax}

__device__ __forceinline__ int xbucket(float x) {
    int bk = (int)floorf((x + 4.0f) * (NBUCKET / 8.0f));
    return max(0, min(NBUCKET - 1, bk));
}
// monotone u32 mapping of float (handles negatives)
__device__ __forceinline__ unsigned ymap(float y) {
    unsigned u = __float_as_uint(y);
    return (u & 0x80000000u) ? ~u : (u | 0x80000000u);
}

// ---------------------------------------------------------------------------
// K0a: counting-sort points of each graph by x-bucket (1024 buckets),
// w = |p|^2 with exact reference rounding (no contraction).
// ---------------------------------------------------------------------------
__global__ void __launch_bounds__(256) sortA_kernel(const float* __restrict__ pos) {
    __shared__ int cnt[NBUCKET];
    __shared__ int tsum[256];
    __shared__ int off[NBUCKET];

    const int b   = blockIdx.x;
    const int tid = threadIdx.x;        // 256 threads
    const float* pg = pos + (size_t)b * NODES * 3;

#pragma unroll
    for (int i = 0; i < NBUCKET / 256; ++i) cnt[tid + i * 256] = 0;
    __syncthreads();

    for (int j = tid; j < NODES; j += 256)
        atomicAdd(&cnt[xbucket(pg[3 * j])], 1);
    __syncthreads();

    {   // two-level exclusive prefix: thread t owns bins [4t, 4t+4)
        int c0 = cnt[4 * tid], c1 = cnt[4 * tid + 1];
        int c2 = cnt[4 * tid + 2], c3 = cnt[4 * tid + 3];
        tsum[tid] = c0 + c1 + c2 + c3;
        __syncthreads();
        for (int d = 1; d < 256; d <<= 1) {
            int v = (tid >= d) ? tsum[tid - d] : 0;
            __syncthreads();
            tsum[tid] += v;
            __syncthreads();
        }
        int base = tsum[tid] - (c0 + c1 + c2 + c3);
        off[4 * tid]     = base;
        off[4 * tid + 1] = base + c0;
        off[4 * tid + 2] = base + c0 + c1;
        off[4 * tid + 3] = base + c0 + c1 + c2;
    }
    __syncthreads();

    for (int j = tid; j < NODES; j += 256) {
        float x = pg[3 * j], y = pg[3 * j + 1], z = pg[3 * j + 2];
        float w = __fadd_rn(__fadd_rn(__fmul_rn(x, x), __fmul_rn(y, y)),
                            __fmul_rn(z, z));        // == jnp.sum(pos*pos)
        int p = atomicAdd(&off[xbucket(x)], 1);
        g_spos[b * NODES + p] = make_float4(x, y, z, w);
        g_sidx[b * NODES + p] = j;
    }
}

// ---------------------------------------------------------------------------
// K0b: per-slab y-sort, warp-per-slab over the whole problem (1024 warps).
// Warp-bitonic sort 64 keys (ymap<<32 | graph-local rank), exact ties by
// rank; emits g_spos2/g_sid2 and exact per-slab x-min/max.
// ---------------------------------------------------------------------------
__global__ void __launch_bounds__(256) sortB_kernel(int dummy) {
    const int tid  = threadIdx.x;
    const int gslab = blockIdx.x * 8 + (tid >> 5);   // global slab id
    const int b = gslab / SLABS;
    const int s = gslab % SLABS;
    const int l = tid & 31;

    int base = b * NODES + s * SLABN;
    float4 f0 = g_spos[base + l];
    float4 f1 = g_spos[base + 32 + l];

    // exact slab x-range
    float xl = fminf(f0.x, f1.x), xh = fmaxf(f0.x, f1.x);
#pragma unroll
    for (int o = 16; o; o >>= 1) {
        xl = fminf(xl, __shfl_xor_sync(0xffffffffu, xl, o));
        xh = fmaxf(xh, __shfl_xor_sync(0xffffffffu, xh, o));
    }
    if (l == 0) {
        g_slabx[(b * SLABS + s) * 2]     = xl;
        g_slabx[(b * SLABS + s) * 2 + 1] = xh;
    }

    uint64_t v0 = ((uint64_t)ymap(f0.y) << 32) | (unsigned)(s * SLABN + l);
    uint64_t v1 = ((uint64_t)ymap(f1.y) << 32) | (unsigned)(s * SLABN + 32 + l);
#pragma unroll
    for (int k = 2; k <= 64; k <<= 1) {
#pragma unroll
        for (int j = k >> 1; j > 0; j >>= 1) {
            if (j == 32) {                 // only in k==64 stage, ascending
                uint64_t mn = v0 < v1 ? v0 : v1;
                uint64_t mx = v0 < v1 ? v1 : v0;
                v0 = mn; v1 = mx;
            } else {
                uint64_t w0 = __shfl_xor_sync(0xffffffffu, v0, j);
                bool asc0 = ((l & k) == 0);
                bool keep0 = (((l & j) == 0) == asc0);
                bool lt0 = v0 < w0;
                v0 = (keep0 == lt0) ? v0 : w0;
                uint64_t w1 = __shfl_xor_sync(0xffffffffu, v1, j);
                bool asc1 = (((32 + l) & k) == 0);
                bool keep1 = (((l & j) == 0) == asc1);
                bool lt1 = v1 < w1;
                v1 = (keep1 == lt1) ? v1 : w1;
            }
        }
    }
    int r0 = (int)(v0 & 0xFFFFu), r1 = (int)(v1 & 0xFFFFu);
    g_spos2[base + l]      = g_spos[b * NODES + r0];
    g_sid2 [base + l]      = g_sidx[b * NODES + r0];
    g_spos2[base + 32 + l] = g_spos[b * NODES + r1];
    g_sid2 [base + 32 + l] = g_sidx[b * NODES + r1];
}

// ---------------------------------------------------------------------------
// K1: 2-D pruned kNN (R13 structure). Thread-per-query; tile = 4 slabs;
// lanes grouped by qy (bitonic on tile queries) so warp y-windows overlap.
//   per slab: gx exact from slab x-range; warp binary-search to
//   ystart = min_lane(qy - sqrt_ru(thr_lane + margin))  [tighter than
//   min(qy) - sqrt(max thr); still safe: a candidate below ystart is below
//   every lane's own pruning bound]; scan upward in 4-candidate groups;
//   exit when all lanes (y_last - qy)^2 + gx^2 >= thr + margin.
//   slab expansion with exact suffix-min / prefix-max x bounds.
// d2 = (qsq+w) - 2*dot with reference rounding; self excluded by rank.
// ---------------------------------------------------------------------------
__global__ void __launch_bounds__(QPB) knn_kernel(int dummy) {
    extern __shared__ float4 sm[];
    float4*          sp     = sm;                           // 4096 float4 (64KB)
    unsigned short*  ssid16 = (unsigned short*)(sm + NODES); // 8KB
    __shared__ uint64_t skey[QPB];
    __shared__ float sxlo[SLABS], sxhi[SLABS], sufmin[SLABS], prefmax[SLABS];

    const int tilesPerGraph = NODES / QPB;  // 16
    const int b    = blockIdx.x / tilesPerGraph;
    const int tile = blockIdx.x % tilesPerGraph;
    const int tid  = threadIdx.x;
    const int gbase = b * NODES;

    // ---- fused zeroing of accumulators + counts ----
    {
        float4 z = make_float4(0.f, 0.f, 0.f, 0.f);
        int nb = blockIdx.x * QPB;
        float4* dst = reinterpret_cast<float4*>(g_sum) + (size_t)nb * (FEATS / 4);
#pragma unroll
        for (int i = 0; i < 16; ++i) dst[i * QPB + tid] = z;
        g_cnt[nb + tid] = 0;
    }

    // ---- stage slab-sorted positions + ids + slab ranges ----
    for (int i = tid; i < NODES; i += QPB) {
        sp[i] = g_spos2[gbase + i];
        ssid16[i] = (unsigned short)g_sid2[gbase + i];
    }
    if (tid < SLABS) {
        sxlo[tid] = g_slabx[(b * SLABS + tid) * 2];
        sxhi[tid] = g_slabx[(b * SLABS + tid) * 2 + 1];
    }
    __syncthreads();
    if (tid == 0) {
        float m = 1e30f;
        for (int s = SLABS - 1; s >= 0; --s) { m = fminf(m, sxlo[s]); sufmin[s] = m; }
        float M = -1e30f;
        for (int s = 0; s < SLABS; ++s) { M = fmaxf(M, sxhi[s]); prefmax[s] = M; }
    }
    __syncthreads();

    // ---- lane grouping: bitonic sort tile queries by qy ----
    {
        int qr0 = tile * QPB + tid;
        skey[tid] = ((uint64_t)ymap(sp[qr0].y) << 32) | (unsigned)qr0;
    }
    __syncthreads();
    for (int k = 2; k <= QPB; k <<= 1) {
        for (int j = k >> 1; j > 0; j >>= 1) {
            int ixj = tid ^ j;
            if (ixj > tid) {
                uint64_t a = skey[tid], c = skey[ixj];
                bool asc = ((tid & k) == 0);
                if ((a > c) == asc) { skey[tid] = c; skey[ixj] = a; }
            }
            __syncthreads();
        }
    }

    // ---- own query ----
    const int qr = (int)(unsigned)(skey[tid] & 0xffffffffu);
    float4 qv = sp[qr];
    const float qx = qv.x, qyv = qv.y, qz = qv.z, qsq = qv.w;

    float kdd[KNN_K];
    int   kdi[KNN_K];
#pragma unroll
    for (int t = 0; t < KNN_K; ++t) { kdd[t] = __int_as_float(0x7f800000); kdi[t] = 0; }
    float thr = __int_as_float(0x7f800000);

    auto scan_slab = [&](int s) {
        float gx = fmaxf(fmaxf(sxlo[s] - qx, qx - sxhi[s]), 0.0f);
        float gx2 = gx * gx;
        // per-lane pruning bound, warp-min (tighter than min(qy)-sqrt(max thr))
        float ys = qyv - __fsqrt_ru(thr + EXIT_MARGIN);   // -inf safe when thr=inf
#pragma unroll
        for (int o = 16; o; o >>= 1)
            ys = fminf(ys, __shfl_xor_sync(0xffffffffu, ys, o));
        float ystart = ys;
        const float4* sb = sp + s * SLABN;
        int lo = 0;
#pragma unroll
        for (int st = 32; st; st >>= 1) {
            int m = lo + st;
            if (sb[m - 1].y < ystart) lo = m;   // warp-uniform; lo <= 64
        }
        for (int i = (lo & ~3); i < SLABN; i += 4) {
            float ylast = 0.0f;
#pragma unroll
            for (int u = 0; u < 4; ++u) {
                int idx = i + u;
                float4 p = sb[idx];
                float dot = __fmaf_rn(qz, p.z, __fmaf_rn(qyv, p.y, __fmul_rn(qx, p.x)));
                float d2  = __fmaf_rn(-2.0f, dot, __fadd_rn(qsq, p.w));
                int rank = s * SLABN + idx;
                if (d2 < thr && rank != qr) {
                    float cd = d2; int ci = (int)ssid16[rank];
#pragma unroll
                    for (int t = 0; t < KNN_K; ++t) {
                        bool sw = cd < kdd[t];
                        float fn = sw ? cd : kdd[t]; float fx = sw ? kdd[t] : cd;
                        int   ii = sw ? ci : kdi[t]; int   ix = sw ? kdi[t] : ci;
                        kdd[t] = fn; kdi[t] = ii; cd = fx; ci = ix;
                    }
                    thr = kdd[KNN_K - 1];
                }
                ylast = p.y;
            }
            float g = fmaxf(ylast - qyv, 0.0f);
            if (__all_sync(0xffffffffu,
                           __fmaf_rn(g, g, gx2) >= thr + EXIT_MARGIN)) break;
        }
    };

    // own tile's 4 slabs (contain every lane's own slab)
    const int s0 = tile * 4;
#pragma unroll
    for (int s = s0; s < s0 + 4; ++s) scan_slab(s);

    // upward slab expansion with exact suffix-min bound
    for (int s = s0 + 4; s < SLABS; ++s) {
        float gf = fmaxf(sufmin[s] - qx, 0.0f);
        if (__all_sync(0xffffffffu, gf * gf >= thr + EXIT_MARGIN)) break;
        scan_slab(s);
    }
    // downward slab expansion with exact prefix-max bound
    for (int s = s0 - 1; s >= 0; --s) {
        float gf = fmaxf(qx - prefmax[s], 0.0f);
        if (__all_sync(0xffffffffu, gf * gf >= thr + EXIT_MARGIN)) break;
        scan_slab(s);
    }

    // ---- write neighbor list (stride 12) for this query's ORIGINAL node ----
    const int my_oid = gbase + (int)ssid16[qr];
    int* gn = reinterpret_cast<int*>(g_nbr4);
#pragma unroll
    for (int t = 0; t < KNN_K; ++t)
        gn[my_oid * NBR_STRIDE + t] = gbase + kdi[t];
}

// ---------------------------------------------------------------------------
// K2: scatter x[query] into g_sum[neighbor] with vectorized L2 reductions,
// plus reverse-degree counting. Neighbor list loaded as 3x int4.
// ---------------------------------------------------------------------------
__global__ void scatter_kernel(const float* __restrict__ x, int total) {
    int t = blockIdx.x * blockDim.x + threadIdx.x;
    int q = t >> 4;
    int c = t & 15;
    if (q >= total) return;

    float4 v = reinterpret_cast<const float4*>(x)[q * (FEATS / 4) + c];
    const int4* nb4 = &g_nbr4[q * 3];
    int4 A = nb4[0], B = nb4[1], C = nb4[2];
    int js[KNN_K] = {A.x, A.y, A.z, A.w, B.x, B.y, B.z, B.w, C.x, C.y};

#pragma unroll
    for (int n = 0; n < KNN_K; ++n) {
        int j = js[n];
        float* p = g_sum + (size_t)j * FEATS + c * 4;
        asm volatile("red.global.add.v4.f32 [%0], {%1, %2, %3, %4};"
                     :: "l"(p), "f"(v.x), "f"(v.y), "f"(v.z), "f"(v.w)
                     : "memory");
        if (c == 0)
            asm volatile("red.global.add.u32 [%0], %1;"
                         :: "l"(&g_cnt[j]), "r"(1) : "memory");
    }
}

// ---------------------------------------------------------------------------
// K3: out[r] = sum_d | x[r,d] - sum[r,d] / max(cnt[r],1) |   (warp per node)
// ---------------------------------------------------------------------------
__global__ void out_kernel(const float* __restrict__ x, float* __restrict__ out,
                           int total) {
    int node = (blockIdx.x * blockDim.x + threadIdx.x) >> 5;
    int lane = threadIdx.x & 31;
    if (node >= total) return;

    float c   = (float)g_cnt[node];
    float inv = 1.0f / fmaxf(c, 1.0f);

    const float* xr = x + (size_t)node * FEATS;
    const float* sr = g_sum + (size_t)node * FEATS;

    float acc = fabsf(xr[lane]      - sr[lane]      * inv)
              + fabsf(xr[lane + 32] - sr[lane + 32] * inv);
#pragma unroll
    for (int o = 16; o > 0; o >>= 1) acc += __shfl_xor_sync(0xffffffffu, acc, o);
    if (lane == 0) out[node] = acc;
}

// ---------------------------------------------------------------------------
extern "C" void kernel_launch(void* const* d_in, const int* in_sizes, int n_in,
                              void* d_out, int out_size) {
    const float* x   = (const float*)d_in[0];   // [total, 64] fp32
    const float* pos = (const float*)d_in[1];   // [total, 3]  fp32

    const int total = in_sizes[0] / FEATS;      // 65536
    float* out = (float*)d_out;

    // K0a: x counting sort per graph (16 blocks)
    sortA_kernel<<<BGRAPHS, 256>>>(pos);

    // K0b: per-slab y-sort, warp-per-slab (128 blocks x 8 warps = 1024 slabs)
    sortB_kernel<<<BGRAPHS * SLABS / 8, 256>>>(0);

    // K1: 2-D pruned kNN (dynamic smem 72KB)
    size_t smem = (size_t)NODES * sizeof(float4) + NODES * sizeof(unsigned short);
    cudaFuncSetAttribute(knn_kernel, cudaFuncAttributeMaxDynamicSharedMemorySize,
                         (int)smem);
    knn_kernel<<<total / QPB, QPB, smem>>>(0);

    // K2: vectorized atomic scatter + counts (16 lanes per query)
    int threads2 = total * 16;
    scatter_kernel<<<(threads2 + 127) / 128, 128>>>(x, total);

    // K3: finalize L1 norm (warp per node)
    out_kernel<<<(total * 32 + 255) / 256, 256>>>(x, out, total);
}

// round 17
// speedup vs baseline: 1.4044x; 1.0854x over previous
#include <cuda_runtime.h>
#include <cuda_bf16.h>
#include <cstdint>

// Problem constants: B=16 graphs, N=4096 nodes/graph, 64 features, k=10.
#define KNN_K      10
#define BGRAPHS    16
#define FEATS      64
#define MAX_TOTAL  65536
#define NODES      4096
#define QPB        256            // queries per block == threads per block (knn)
#define NBUCKET    1024
#define SLABS      64             // x-slabs per graph
#define SLABN      64             // points per slab
#define REVCAP     64             // reverse-adjacency capacity per node
#define EXIT_MARGIN 1e-4f         // covers f32 cancellation in computed d2

// Scratch (device globals: no allocation allowed in kernel_launch)
__device__ int    g_cnt[MAX_TOTAL];              // reverse-degree counts
__device__ int    g_rev[MAX_TOTAL * REVCAP];     // reverse adjacency (16 MB)
__device__ float4 g_spos[MAX_TOTAL];             // x-sorted {x,y,z,|p|^2}
__device__ int    g_sidx[MAX_TOTAL];             // x-rank -> orig local idx
__device__ float4 g_spos2[MAX_TOTAL];            // slab/y-sorted positions
__device__ int    g_sid2[MAX_TOTAL];             // slab/y-rank -> orig local idx
__device__ float  g_slabx[BGRAPHS * SLABS * 2];  // per-slab exact {xmin, xmax}

__device__ __forceinline__ int xbucket(float x) {
    int bk = (int)floorf((x + 4.0f) * (NBUCKET / 8.0f));
    return max(0, min(NBUCKET - 1, bk));
}
// monotone u32 mapping of float (handles negatives)
__device__ __forceinline__ unsigned ymap(float y) {
    unsigned u = __float_as_uint(y);
    return (u & 0x80000000u) ? ~u : (u | 0x80000000u);
}

// ---------------------------------------------------------------------------
// K0a: counting-sort points of each graph by x-bucket (1024 buckets),
// w = |p|^2 with exact reference rounding (no contraction).
// ---------------------------------------------------------------------------
__global__ void __launch_bounds__(256) sortA_kernel(const float* __restrict__ pos) {
    __shared__ int cnt[NBUCKET];
    __shared__ int tsum[256];
    __shared__ int off[NBUCKET];

    const int b   = blockIdx.x;
    const int tid = threadIdx.x;        // 256 threads
    const float* pg = pos + (size_t)b * NODES * 3;

#pragma unroll
    for (int i = 0; i < NBUCKET / 256; ++i) cnt[tid + i * 256] = 0;
    __syncthreads();

    for (int j = tid; j < NODES; j += 256)
        atomicAdd(&cnt[xbucket(pg[3 * j])], 1);
    __syncthreads();

    {   // two-level exclusive prefix: thread t owns bins [4t, 4t+4)
        int c0 = cnt[4 * tid], c1 = cnt[4 * tid + 1];
        int c2 = cnt[4 * tid + 2], c3 = cnt[4 * tid + 3];
        tsum[tid] = c0 + c1 + c2 + c3;
        __syncthreads();
        for (int d = 1; d < 256; d <<= 1) {
            int v = (tid >= d) ? tsum[tid - d] : 0;
            __syncthreads();
            tsum[tid] += v;
            __syncthreads();
        }
        int base = tsum[tid] - (c0 + c1 + c2 + c3);
        off[4 * tid]     = base;
        off[4 * tid + 1] = base + c0;
        off[4 * tid + 2] = base + c0 + c1;
        off[4 * tid + 3] = base + c0 + c1 + c2;
    }
    __syncthreads();

    for (int j = tid; j < NODES; j += 256) {
        float x = pg[3 * j], y = pg[3 * j + 1], z = pg[3 * j + 2];
        float w = __fadd_rn(__fadd_rn(__fmul_rn(x, x), __fmul_rn(y, y)),
                            __fmul_rn(z, z));        // == jnp.sum(pos*pos)
        int p = atomicAdd(&off[xbucket(x)], 1);
        g_spos[b * NODES + p] = make_float4(x, y, z, w);
        g_sidx[b * NODES + p] = j;
    }
}

// ---------------------------------------------------------------------------
// K0b: per-slab y-sort, warp-per-slab (1024 warps). Also zeroes g_cnt
// (stream-ordered BEFORE knn, whose epilogue atomics build reverse lists).
// ---------------------------------------------------------------------------
__global__ void __launch_bounds__(256) sortB_kernel(int dummy) {
    const int tid  = threadIdx.x;
    const int gslab = blockIdx.x * 8 + (tid >> 5);   // global slab id
    const int b = gslab / SLABS;
    const int s = gslab % SLABS;
    const int l = tid & 31;

    // zero reverse-degree counts (65536 ints over 128 blocks x 256 threads)
    {
        int i = blockIdx.x * 256 + tid;
        g_cnt[i] = 0;
        g_cnt[i + 32768] = 0;
    }

    int base = b * NODES + s * SLABN;
    float4 f0 = g_spos[base + l];
    float4 f1 = g_spos[base + 32 + l];

    // exact slab x-range
    float xl = fminf(f0.x, f1.x), xh = fmaxf(f0.x, f1.x);
#pragma unroll
    for (int o = 16; o; o >>= 1) {
        xl = fminf(xl, __shfl_xor_sync(0xffffffffu, xl, o));
        xh = fmaxf(xh, __shfl_xor_sync(0xffffffffu, xh, o));
    }
    if (l == 0) {
        g_slabx[(b * SLABS + s) * 2]     = xl;
        g_slabx[(b * SLABS + s) * 2 + 1] = xh;
    }

    uint64_t v0 = ((uint64_t)ymap(f0.y) << 32) | (unsigned)(s * SLABN + l);
    uint64_t v1 = ((uint64_t)ymap(f1.y) << 32) | (unsigned)(s * SLABN + 32 + l);
#pragma unroll
    for (int k = 2; k <= 64; k <<= 1) {
#pragma unroll
        for (int j = k >> 1; j > 0; j >>= 1) {
            if (j == 32) {                 // only in k==64 stage, ascending
                uint64_t mn = v0 < v1 ? v0 : v1;
                uint64_t mx = v0 < v1 ? v1 : v0;
                v0 = mn; v1 = mx;
            } else {
                uint64_t w0 = __shfl_xor_sync(0xffffffffu, v0, j);
                bool asc0 = ((l & k) == 0);
                bool keep0 = (((l & j) == 0) == asc0);
                bool lt0 = v0 < w0;
                v0 = (keep0 == lt0) ? v0 : w0;
                uint64_t w1 = __shfl_xor_sync(0xffffffffu, v1, j);
                bool asc1 = (((32 + l) & k) == 0);
                bool keep1 = (((l & j) == 0) == asc1);
                bool lt1 = v1 < w1;
                v1 = (keep1 == lt1) ? v1 : w1;
            }
        }
    }
    int r0 = (int)(v0 & 0xFFFFu), r1 = (int)(v1 & 0xFFFFu);
    g_spos2[base + l]      = g_spos[b * NODES + r0];
    g_sid2 [base + l]      = g_sidx[b * NODES + r0];
    g_spos2[base + 32 + l] = g_spos[b * NODES + r1];
    g_sid2 [base + 32 + l] = g_sidx[b * NODES + r1];
}

// ---------------------------------------------------------------------------
// K1: 2-D pruned kNN (R16 structure, unchanged scan). Thread-per-query;
// tile = 4 slabs; lanes grouped by qy. Epilogue now builds the REVERSE
// adjacency directly: for each of the 10 neighbors j, atomically append my
// original node id to g_rev[j]. (Forward lists are never materialized.)
// ---------------------------------------------------------------------------
__global__ void __launch_bounds__(QPB) knn_kernel(int dummy) {
    extern __shared__ float4 sm[];
    float4*          sp     = sm;                           // 4096 float4 (64KB)
    unsigned short*  ssid16 = (unsigned short*)(sm + NODES); // 8KB
    __shared__ uint64_t skey[QPB];
    __shared__ float sxlo[SLABS], sxhi[SLABS], sufmin[SLABS], prefmax[SLABS];

    const int tilesPerGraph = NODES / QPB;  // 16
    const int b    = blockIdx.x / tilesPerGraph;
    const int tile = blockIdx.x % tilesPerGraph;
    const int tid  = threadIdx.x;
    const int gbase = b * NODES;

    // ---- stage slab-sorted positions + ids + slab ranges ----
    for (int i = tid; i < NODES; i += QPB) {
        sp[i] = g_spos2[gbase + i];
        ssid16[i] = (unsigned short)g_sid2[gbase + i];
    }
    if (tid < SLABS) {
        sxlo[tid] = g_slabx[(b * SLABS + tid) * 2];
        sxhi[tid] = g_slabx[(b * SLABS + tid) * 2 + 1];
    }
    __syncthreads();
    if (tid == 0) {
        float m = 1e30f;
        for (int s = SLABS - 1; s >= 0; --s) { m = fminf(m, sxlo[s]); sufmin[s] = m; }
        float M = -1e30f;
        for (int s = 0; s < SLABS; ++s) { M = fmaxf(M, sxhi[s]); prefmax[s] = M; }
    }
    __syncthreads();

    // ---- lane grouping: bitonic sort tile queries by qy ----
    {
        int qr0 = tile * QPB + tid;
        skey[tid] = ((uint64_t)ymap(sp[qr0].y) << 32) | (unsigned)qr0;
    }
    __syncthreads();
    for (int k = 2; k <= QPB; k <<= 1) {
        for (int j = k >> 1; j > 0; j >>= 1) {
            int ixj = tid ^ j;
            if (ixj > tid) {
                uint64_t a = skey[tid], c = skey[ixj];
                bool asc = ((tid & k) == 0);
                if ((a > c) == asc) { skey[tid] = c; skey[ixj] = a; }
            }
            __syncthreads();
        }
    }

    // ---- own query ----
    const int qr = (int)(unsigned)(skey[tid] & 0xffffffffu);
    float4 qv = sp[qr];
    const float qx = qv.x, qyv = qv.y, qz = qv.z, qsq = qv.w;

    float kdd[KNN_K];
    int   kdi[KNN_K];
#pragma unroll
    for (int t = 0; t < KNN_K; ++t) { kdd[t] = __int_as_float(0x7f800000); kdi[t] = 0; }
    float thr = __int_as_float(0x7f800000);

    auto scan_slab = [&](int s) {
        float gx = fmaxf(fmaxf(sxlo[s] - qx, qx - sxhi[s]), 0.0f);
        float gx2 = gx * gx;
        // per-lane pruning bound, warp-min
        float ys = qyv - __fsqrt_ru(thr + EXIT_MARGIN);   // -inf safe when thr=inf
#pragma unroll
        for (int o = 16; o; o >>= 1)
            ys = fminf(ys, __shfl_xor_sync(0xffffffffu, ys, o));
        float ystart = ys;
        const float4* sb = sp + s * SLABN;
        int lo = 0;
#pragma unroll
        for (int st = 32; st; st >>= 1) {
            int m = lo + st;
            if (sb[m - 1].y < ystart) lo = m;   // warp-uniform; lo <= 64
        }
        for (int i = (lo & ~3); i < SLABN; i += 4) {
            float ylast = 0.0f;
#pragma unroll
            for (int u = 0; u < 4; ++u) {
                int idx = i + u;
                float4 p = sb[idx];
                float dot = __fmaf_rn(qz, p.z, __fmaf_rn(qyv, p.y, __fmul_rn(qx, p.x)));
                float d2  = __fmaf_rn(-2.0f, dot, __fadd_rn(qsq, p.w));
                int rank = s * SLABN + idx;
                if (d2 < thr && rank != qr) {
                    float cd = d2; int ci = (int)ssid16[rank];
#pragma unroll
                    for (int t = 0; t < KNN_K; ++t) {
                        bool sw = cd < kdd[t];
                        float fn = sw ? cd : kdd[t]; float fx = sw ? kdd[t] : cd;
                        int   ii = sw ? ci : kdi[t]; int   ix = sw ? kdi[t] : ci;
                        kdd[t] = fn; kdi[t] = ii; cd = fx; ci = ix;
                    }
                    thr = kdd[KNN_K - 1];
                }
                ylast = p.y;
            }
            float g = fmaxf(ylast - qyv, 0.0f);
            if (__all_sync(0xffffffffu,
                           __fmaf_rn(g, g, gx2) >= thr + EXIT_MARGIN)) break;
        }
    };

    // own tile's 4 slabs
    const int s0 = tile * 4;
#pragma unroll
    for (int s = s0; s < s0 + 4; ++s) scan_slab(s);

    // upward slab expansion with exact suffix-min bound
    for (int s = s0 + 4; s < SLABS; ++s) {
        float gf = fmaxf(sufmin[s] - qx, 0.0f);
        if (__all_sync(0xffffffffu, gf * gf >= thr + EXIT_MARGIN)) break;
        scan_slab(s);
    }
    // downward slab expansion with exact prefix-max bound
    for (int s = s0 - 1; s >= 0; --s) {
        float gf = fmaxf(qx - prefmax[s], 0.0f);
        if (__all_sync(0xffffffffu, gf * gf >= thr + EXIT_MARGIN)) break;
        scan_slab(s);
    }

    // ---- epilogue: append my original id to each neighbor's reverse list ----
    const int my_oid = gbase + (int)ssid16[qr];
#pragma unroll
    for (int t = 0; t < KNN_K; ++t) {
        int j = gbase + kdi[t];
        int pos = atomicAdd(&g_cnt[j], 1);
        if (pos < REVCAP)
            g_rev[(size_t)j * REVCAP + pos] = my_oid;
    }
}

// ---------------------------------------------------------------------------
// K2: fused gather + L1-norm output (replaces scatter + out kernels).
// Warp per node: sum x over the node's reverse list (coalesced row loads),
// mean with max(cnt,1), L1 distance to own features, warp-reduce, store.
// ---------------------------------------------------------------------------
__global__ void gather_kernel(const float* __restrict__ x,
                              float* __restrict__ out, int total) {
    int node = (blockIdx.x * blockDim.x + threadIdx.x) >> 5;
    int lane = threadIdx.x & 31;
    if (node >= total) return;

    int cnt = g_cnt[node];
    int m = min(cnt, REVCAP);
    const int* rl = g_rev + (size_t)node * REVCAP;

    float s0 = 0.0f, s1 = 0.0f;
    for (int c = 0; c < m; ++c) {
        int q = rl[c];
        const float* xr = x + (size_t)q * FEATS;
        s0 += xr[lane];
        s1 += xr[lane + 32];
    }

    float inv = 1.0f / fmaxf((float)cnt, 1.0f);
    const float* xn = x + (size_t)node * FEATS;
    float acc = fabsf(xn[lane]      - s0 * inv)
              + fabsf(xn[lane + 32] - s1 * inv);
#pragma unroll
    for (int o = 16; o > 0; o >>= 1) acc += __shfl_xor_sync(0xffffffffu, acc, o);
    if (lane == 0) out[node] = acc;
}

// ---------------------------------------------------------------------------
extern "C" void kernel_launch(void* const* d_in, const int* in_sizes, int n_in,
                              void* d_out, int out_size) {
    const float* x   = (const float*)d_in[0];   // [total, 64] fp32
    const float* pos = (const float*)d_in[1];   // [total, 3]  fp32

    const int total = in_sizes[0] / FEATS;      // 65536
    float* out = (float*)d_out;

    // K0a: x counting sort per graph (16 blocks)
    sortA_kernel<<<BGRAPHS, 256>>>(pos);

    // K0b: per-slab y-sort + g_cnt zeroing (128 blocks x 8 warps)
    sortB_kernel<<<BGRAPHS * SLABS / 8, 256>>>(0);

    // K1: 2-D pruned kNN + reverse-adjacency build (dynamic smem 72KB)
    size_t smem = (size_t)NODES * sizeof(float4) + NODES * sizeof(unsigned short);
    cudaFuncSetAttribute(knn_kernel, cudaFuncAttributeMaxDynamicSharedMemorySize,
                         (int)smem);
    knn_kernel<<<total / QPB, QPB, smem>>>(0);

    // K2: fused gather-mean + L1 output (warp per node)
    gather_kernel<<<(total * 32 + 255) / 256, 256>>>(x, out, total);
}